// round 7
// baseline (speedup 1.0000x reference)
#include <cuda_runtime.h>
#include <math.h>

#define BSN 2500   // nodes
#define TT  400    // timesteps
#define DD  16     // input dim
#define HH  32     // hidden dim
#define G4  128    // 4*H

#define NCTA     125
#define ROWS     20          // 125*20 = 2500
#define NTHREADS 512
#define NWARP    16

#define SMEM_FLOATS (BSN*ROWS + 4*ROWS*HH + ROWS*G4 + ROWS*HH + ROWS*HH + ROWS*DD)
#define SMEM_BYTES  (SMEM_FLOATS * 4)

__device__ unsigned int g_bar;
__device__ float g_q[2][BSN * HH];   // double-buffered q_t

__device__ __forceinline__ unsigned long long pack2(float x, float y) {
    unsigned long long r;
    asm("mov.b64 %0, {%1, %2};" : "=l"(r) : "f"(x), "f"(y));
    return r;
}
__device__ __forceinline__ void ffma2(unsigned long long& d,
                                      unsigned long long a, unsigned long long b) {
    asm("fma.rn.f32x2 %0, %1, %2, %0;" : "+l"(d) : "l"(a), "l"(b));
}
__device__ __forceinline__ float2 unpack2(unsigned long long v) {
    float2 r;
    asm("mov.b64 {%0, %1}, %2;" : "=f"(r.x), "=f"(r.y) : "l"(v));
    return r;
}
// fast activations: MUFU-based, rel err ~1e-7 (vs 1e-3 budget)
__device__ __forceinline__ float sigmoid_f(float x) {
    return __fdividef(1.0f, 1.0f + __expf(-x));
}
__device__ __forceinline__ float tanh_f(float x) {
    return 1.0f - __fdividef(2.0f, __expf(2.0f * x) + 1.0f);
}

__device__ __forceinline__ void named_bar(int id) {
    asm volatile("bar.sync %0, 64;" :: "r"(id) : "memory");
}

__device__ __forceinline__ void grid_barrier(unsigned epoch) {
    __threadfence();
    __syncthreads();
    if (threadIdx.x == 0) {
        atomicAdd(&g_bar, 1u);
        const unsigned target = epoch * (unsigned)NCTA;
        unsigned v;
        do {
            asm volatile("ld.acquire.gpu.global.u32 %0, [%1];"
                         : "=r"(v) : "l"(&g_bar) : "memory");
        } while (v < target);
    }
    __syncthreads();
}

// next-step gates (g4s = b + x@W_ih + h@W_hh) and q = tanh(h@W_q + b_q)
__device__ __forceinline__ void prep_next(
    int tid, int row0, const float* xs, const float* hs, float* g4s,
    const float* W_ih, const float* W_hh, const float* b,
    const float* W_q, const float* b_q, float* qdst)
{
    const int j  = tid & 127;
    const int m0 = (tid >> 7) * (ROWS / 4);
    float a5[ROWS / 4];
    const float bj = b[j];
    #pragma unroll
    for (int mm = 0; mm < ROWS / 4; mm++) a5[mm] = bj;
    #pragma unroll
    for (int kk = 0; kk < HH; kk++) {
        const float w = W_hh[kk * G4 + j];
        #pragma unroll
        for (int mm = 0; mm < ROWS / 4; mm++) a5[mm] += hs[(m0 + mm) * HH + kk] * w;
    }
    #pragma unroll
    for (int d = 0; d < DD; d++) {
        const float w = W_ih[d * G4 + j];
        #pragma unroll
        for (int mm = 0; mm < ROWS / 4; mm++) a5[mm] += xs[(m0 + mm) * DD + d] * w;
    }
    #pragma unroll
    for (int mm = 0; mm < ROWS / 4; mm++) g4s[(m0 + mm) * G4 + j] = a5[mm];

    for (int e = tid; e < ROWS * HH; e += NTHREADS) {
        const int m = e >> 5, n = e & 31;
        float a = b_q[n];
        #pragma unroll
        for (int kk = 0; kk < HH; kk++) a += hs[m * HH + kk] * W_q[kk * HH + n];
        __stcg(&qdst[(size_t)(row0 + m) * HH + n], tanh_f(a));
    }
}

__global__ void rgcn_reset() { g_bar = 0u; }

__global__ void __launch_bounds__(NTHREADS, 1)
rgcn_kernel(const float* __restrict__ x,    const float* __restrict__ adj,
            const float* __restrict__ W_ih, const float* __restrict__ W_hh,
            const float* __restrict__ b,    const float* __restrict__ W_q,
            const float* __restrict__ b_q,  const float* __restrict__ W_d,
            const float* __restrict__ b_d,  float* __restrict__ out)
{
    extern __shared__ float smem[];
    float* adjT = smem;                    // [BSN][ROWS]
    float* red  = adjT + BSN * ROWS;       // [4][ROWS][HH]
    float* g4s  = red  + 4 * ROWS * HH;    // [ROWS][G4]
    float* hs   = g4s  + ROWS * G4;        // [ROWS][HH]
    float* cs   = hs   + ROWS * HH;        // [ROWS][HH]
    float* xs   = cs   + ROWS * HH;        // [ROWS][DD]

    const int tid  = threadIdx.x;
    const int lane = tid & 31;
    const int wid  = tid >> 5;
    const int row0 = blockIdx.x * ROWS;

    for (int e = tid; e < ROWS * HH; e += NTHREADS) { hs[e] = 0.0f; cs[e] = 0.0f; }
    for (int e = tid; e < ROWS * BSN; e += NTHREADS) {
        int m = e / BSN;
        int k = e - m * BSN;
        adjT[k * ROWS + m] = adj[(size_t)(row0 + m) * BSN + k];
    }
    for (int e = tid; e < ROWS * DD; e += NTHREADS)
        xs[e] = x[(size_t)(row0 + e / DD) * (TT * DD) + (e & (DD - 1))];
    __syncthreads();

    prep_next(tid, row0, xs, hs, g4s, W_ih, W_hh, b, W_q, b_q, g_q[0]);
    grid_barrier(1);

    const unsigned sA = (unsigned)__cvta_generic_to_shared(adjT);

    for (int t = 0; t < TT; ++t) {
        const float* __restrict__ qr = g_q[t & 1];

        unsigned long long acc[ROWS / 2];
        #pragma unroll
        for (int i = 0; i < ROWS / 2; i++) acc[i] = 0ull;

        const int k0 = (BSN * wid) / NWARP;
        const int k1 = (BSN * (wid + 1)) / NWARP;

        #define ADJ_FMA(KIDX, QQ) do {                                                  \
            unsigned a_off = sA + (unsigned)(KIDX) * (ROWS * 4u);                       \
            unsigned long long a0,a1,a2,a3,a4,a5,a6,a7,a8,a9;                           \
            asm("ld.shared.v2.b64 {%0,%1},[%2];" : "=l"(a0),"=l"(a1) : "r"(a_off));     \
            asm("ld.shared.v2.b64 {%0,%1},[%2];" : "=l"(a2),"=l"(a3) : "r"(a_off+16u)); \
            asm("ld.shared.v2.b64 {%0,%1},[%2];" : "=l"(a4),"=l"(a5) : "r"(a_off+32u)); \
            asm("ld.shared.v2.b64 {%0,%1},[%2];" : "=l"(a6),"=l"(a7) : "r"(a_off+48u)); \
            asm("ld.shared.v2.b64 {%0,%1},[%2];" : "=l"(a8),"=l"(a9) : "r"(a_off+64u)); \
            ffma2(acc[0], a0, QQ); ffma2(acc[1], a1, QQ);                               \
            ffma2(acc[2], a2, QQ); ffma2(acc[3], a3, QQ);                               \
            ffma2(acc[4], a4, QQ); ffma2(acc[5], a5, QQ);                               \
            ffma2(acc[6], a6, QQ); ffma2(acc[7], a7, QQ);                               \
            ffma2(acc[8], a8, QQ); ffma2(acc[9], a9, QQ);                               \
        } while (0)

        {
            const int UNR = 4;              // k's per block
            const int DIST = 2;             // prefetch distance (blocks)
            int k = k0;
            const int nblk = (k1 - k0) / UNR;
            const int kmain = k0 + nblk * UNR;
            float qbuf[DIST][UNR];
            #pragma unroll
            for (int d = 0; d < DIST; d++) {
                const int kb = k0 + d * UNR;
                if (d < nblk) {
                    #pragma unroll
                    for (int i = 0; i < UNR; i++)
                        qbuf[d][i] = __ldcg(qr + (kb + i) * HH + lane);
                }
            }
            int blk = 0;
            while (k < kmain) {
                const int kpre = k + DIST * UNR;
                float qn[UNR];
                if (blk + DIST < nblk) {
                    #pragma unroll
                    for (int i = 0; i < UNR; i++)
                        qn[i] = __ldcg(qr + (kpre + i) * HH + lane);
                }
                #pragma unroll
                for (int i = 0; i < UNR; i++) {
                    const float qi = qbuf[0][i];
                    const unsigned long long qq = pack2(qi, qi);
                    ADJ_FMA(k + i, qq);
                }
                #pragma unroll
                for (int d = 0; d < DIST - 1; d++)
                    #pragma unroll
                    for (int i = 0; i < UNR; i++) qbuf[d][i] = qbuf[d + 1][i];
                #pragma unroll
                for (int i = 0; i < UNR; i++) qbuf[DIST - 1][i] = qn[i];
                k += UNR;
                blk++;
            }
            for (; k < k1; ++k) {
                const float q1 = __ldcg(qr + k * HH + lane);
                const unsigned long long qq = pack2(q1, q1);
                ADJ_FMA(k, qq);
            }
        }
        #undef ADJ_FMA

        // overlap: stage x_{t+1} while reduction chains run
        if (t + 1 < TT) {
            for (int e = tid; e < ROWS * DD; e += NTHREADS)
                xs[e] = x[(size_t)(row0 + e / DD) * (TT * DD) + (t + 1) * DD + (e & (DD - 1))];
        }

        // ---- reduction: 4 independent 4-warp chains, pairwise named barriers ----
        {
            const int s = wid & 3;   // slice / chain id
            if (wid >= 12) {
                float* rb = red + s * ROWS * HH;
                #pragma unroll
                for (int j = 0; j < ROWS / 2; j++) {
                    const float2 v = unpack2(acc[j]);
                    rb[(2 * j) * HH + lane]     = v.x;
                    rb[(2 * j + 1) * HH + lane] = v.y;
                }
                named_bar(1 + s);
            } else if (wid >= 8) {
                named_bar(1 + s);
                float* rb = red + s * ROWS * HH;
                #pragma unroll
                for (int j = 0; j < ROWS / 2; j++) {
                    const float2 v = unpack2(acc[j]);
                    rb[(2 * j) * HH + lane]     += v.x;
                    rb[(2 * j + 1) * HH + lane] += v.y;
                }
                named_bar(5 + s);
            } else if (wid >= 4) {
                named_bar(5 + s);
                float* rb = red + s * ROWS * HH;
                #pragma unroll
                for (int j = 0; j < ROWS / 2; j++) {
                    const float2 v = unpack2(acc[j]);
                    rb[(2 * j) * HH + lane]     += v.x;
                    rb[(2 * j + 1) * HH + lane] += v.y;
                }
                named_bar(9 + s);
            } else {
                named_bar(9 + s);
                float* rb = red + s * ROWS * HH;
                #pragma unroll
                for (int j = 0; j < ROWS / 2; j++) {
                    const float2 v = unpack2(acc[j]);
                    rb[(2 * j) * HH + lane]     += v.x;
                    rb[(2 * j + 1) * HH + lane] += v.y;
                }
            }
        }
        __syncthreads();

        // ---- LSTM epilogue (fast activations) ----
        for (int e = tid; e < ROWS * HH; e += NTHREADS) {
            const int m = e >> 5, n = e & 31;
            const float aggv = red[m * HH + n]
                             + red[1 * ROWS * HH + m * HH + n]
                             + red[2 * ROWS * HH + m * HH + n]
                             + red[3 * ROWS * HH + m * HH + n];
            const float iv = sigmoid_f(g4s[m * G4 + n]);
            const float fv = sigmoid_f(g4s[m * G4 + HH + n]);
            const float gv = tanh_f(g4s[m * G4 + 2 * HH + n]);
            const float ov = sigmoid_f(g4s[m * G4 + 3 * HH + n]);
            const float cv = fv * (cs[e] + aggv) + iv * gv;
            cs[e] = cv;
            hs[e] = ov * tanh_f(cv);
        }
        __syncthreads();

        // ---- dense head ----
        if (tid < ROWS) {
            float a = b_d[0];
            #pragma unroll
            for (int n = 0; n < HH; n++) a += hs[tid * HH + n] * W_d[n];
            out[(size_t)(row0 + tid) * TT + t] = a;
        }

        if (t + 1 < TT) {
            prep_next(tid, row0, xs, hs, g4s, W_ih, W_hh, b, W_q, b_q, g_q[(t + 1) & 1]);
            grid_barrier((unsigned)(t + 2));
        }
    }
}

extern "C" void kernel_launch(void* const* d_in, const int* in_sizes, int n_in,
                              void* d_out, int out_size) {
    (void)in_sizes; (void)n_in; (void)out_size;
    const float* x    = (const float*)d_in[0];
    const float* adj  = (const float*)d_in[1];
    const float* W_ih = (const float*)d_in[2];
    const float* W_hh = (const float*)d_in[3];
    const float* b    = (const float*)d_in[4];
    const float* W_q  = (const float*)d_in[5];
    const float* b_q  = (const float*)d_in[6];
    const float* W_d  = (const float*)d_in[7];
    const float* b_d  = (const float*)d_in[8];
    float* out = (float*)d_out;

    cudaFuncSetAttribute(rgcn_kernel,
                         cudaFuncAttributeMaxDynamicSharedMemorySize, SMEM_BYTES);
    rgcn_reset<<<1, 1>>>();
    rgcn_kernel<<<NCTA, NTHREADS, SMEM_BYTES>>>(x, adj, W_ih, W_hh, b,
                                                W_q, b_q, W_d, b_d, out);
}

// round 8
// speedup vs baseline: 1.0411x; 1.0411x over previous
#include <cuda_runtime.h>
#include <math.h>

#define BSN 2500   // nodes
#define TT  400    // timesteps
#define DD  16     // input dim
#define HH  32     // hidden dim
#define G4  128    // 4*H

#define NCTA     125
#define ROWS     20          // 125*20 = 2500
#define NTHREADS 512
#define NWARP    16

// smem floats: adjT + red(4) + g4s + hs + cs + xs(double)
#define SMEM_FLOATS (BSN*ROWS + 4*ROWS*HH + ROWS*G4 + ROWS*HH + ROWS*HH + 2*ROWS*DD)
#define SMEM_BYTES  (SMEM_FLOATS * 4)

__device__ unsigned int g_bar;
__device__ float g_q[2][BSN * HH];   // double-buffered q_t

__device__ __forceinline__ unsigned long long pack2(float x, float y) {
    unsigned long long r;
    asm("mov.b64 %0, {%1, %2};" : "=l"(r) : "f"(x), "f"(y));
    return r;
}
__device__ __forceinline__ void ffma2(unsigned long long& d,
                                      unsigned long long a, unsigned long long b) {
    asm("fma.rn.f32x2 %0, %1, %2, %0;" : "+l"(d) : "l"(a), "l"(b));
}
__device__ __forceinline__ float2 unpack2(unsigned long long v) {
    float2 r;
    asm("mov.b64 {%0, %1}, %2;" : "=f"(r.x), "=f"(r.y) : "l"(v));
    return r;
}
__device__ __forceinline__ float sigmoid_f(float x) {
    return __fdividef(1.0f, 1.0f + __expf(-x));
}
__device__ __forceinline__ float tanh_f(float x) {
    return 1.0f - __fdividef(2.0f, __expf(2.0f * x) + 1.0f);
}

__device__ __forceinline__ void named_bar(int id) {
    asm volatile("bar.sync %0, 64;" :: "r"(id) : "memory");
}

__device__ __forceinline__ void grid_barrier(unsigned epoch) {
    __threadfence();
    __syncthreads();
    if (threadIdx.x == 0) {
        atomicAdd(&g_bar, 1u);
        const unsigned target = epoch * (unsigned)NCTA;
        unsigned v;
        do {
            asm volatile("ld.acquire.gpu.global.u32 %0, [%1];"
                         : "=r"(v) : "l"(&g_bar) : "memory");
        } while (v < target);
    }
    __syncthreads();
}

// gates for step t, PRE-ACTIVATED into g4s: [i f g o] -> [sig sig tanh sig]
__device__ __forceinline__ void gates_act(
    int tid, const float* xcur, const float* hs, float* g4s,
    const float* __restrict__ W_ih, const float* __restrict__ W_hh,
    const float* __restrict__ b)
{
    const int j  = tid & 127;
    const int m0 = (tid >> 7) * (ROWS / 4);
    float a5[ROWS / 4];
    const float bj = b[j];
    #pragma unroll
    for (int mm = 0; mm < ROWS / 4; mm++) a5[mm] = bj;
    #pragma unroll
    for (int kk = 0; kk < HH; kk++) {
        const float w = W_hh[kk * G4 + j];
        #pragma unroll
        for (int mm = 0; mm < ROWS / 4; mm++) a5[mm] += hs[(m0 + mm) * HH + kk] * w;
    }
    #pragma unroll
    for (int d = 0; d < DD; d++) {
        const float w = W_ih[d * G4 + j];
        #pragma unroll
        for (int mm = 0; mm < ROWS / 4; mm++) a5[mm] += xcur[(m0 + mm) * DD + d] * w;
    }
    const int sect = j >> 5;   // 0:i 1:f 2:g 3:o
    #pragma unroll
    for (int mm = 0; mm < ROWS / 4; mm++) {
        const float v = (sect == 2) ? tanh_f(a5[mm]) : sigmoid_f(a5[mm]);
        g4s[(m0 + mm) * G4 + j] = v;
    }
}

// q_{t+1} = tanh(h@W_q + b_q) -> global (L2)
__device__ __forceinline__ void q_prep(
    int tid, int row0, const float* hs,
    const float* __restrict__ W_q, const float* __restrict__ b_q, float* qdst)
{
    for (int e = tid; e < ROWS * HH; e += NTHREADS) {
        const int m = e >> 5, n = e & 31;
        float a = b_q[n];
        #pragma unroll
        for (int kk = 0; kk < HH; kk++) a += hs[m * HH + kk] * W_q[kk * HH + n];
        __stcg(&qdst[(size_t)(row0 + m) * HH + n], tanh_f(a));
    }
}

__global__ void rgcn_reset() { g_bar = 0u; }

__global__ void __launch_bounds__(NTHREADS, 1)
rgcn_kernel(const float* __restrict__ x,    const float* __restrict__ adj,
            const float* __restrict__ W_ih, const float* __restrict__ W_hh,
            const float* __restrict__ b,    const float* __restrict__ W_q,
            const float* __restrict__ b_q,  const float* __restrict__ W_d,
            const float* __restrict__ b_d,  float* __restrict__ out)
{
    extern __shared__ float smem[];
    float* adjT  = smem;                    // [BSN][ROWS]
    float* red   = adjT + BSN * ROWS;       // [4][ROWS][HH]
    float* g4s   = red  + 4 * ROWS * HH;    // [ROWS][G4] (activated)
    float* hs    = g4s  + ROWS * G4;        // [ROWS][HH]
    float* cs    = hs   + ROWS * HH;        // [ROWS][HH]
    float* xsbuf = cs   + ROWS * HH;        // [2][ROWS][DD]

    const int tid  = threadIdx.x;
    const int lane = tid & 31;
    const int wid  = tid >> 5;
    const int row0 = blockIdx.x * ROWS;

    for (int e = tid; e < ROWS * HH; e += NTHREADS) { hs[e] = 0.0f; cs[e] = 0.0f; }
    for (int e = tid; e < ROWS * BSN; e += NTHREADS) {
        int m = e / BSN;
        int k = e - m * BSN;
        adjT[k * ROWS + m] = adj[(size_t)(row0 + m) * BSN + k];
    }
    for (int e = tid; e < ROWS * DD; e += NTHREADS)
        xsbuf[e] = x[(size_t)(row0 + e / DD) * (TT * DD) + (e & (DD - 1))];
    __syncthreads();

    // q_0 = tanh(0@W_q + b_q)
    q_prep(tid, row0, hs, W_q, b_q, g_q[0]);
    grid_barrier(1);

    const unsigned sA = (unsigned)__cvta_generic_to_shared(adjT);
    const int k0 = (BSN * wid) / NWARP;
    const int k1 = (BSN * (wid + 1)) / NWARP;

    for (int t = 0; t < TT; ++t) {
        const float* __restrict__ qr = g_q[t & 1];

        unsigned long long acc[ROWS / 2];
        #pragma unroll
        for (int i = 0; i < ROWS / 2; i++) acc[i] = 0ull;

        #define ADJ_FMA(KIDX, QQ) do {                                                  \
            unsigned a_off = sA + (unsigned)(KIDX) * (ROWS * 4u);                       \
            unsigned long long a0,a1,a2,a3,a4,a5,a6,a7,a8,a9;                           \
            asm("ld.shared.v2.b64 {%0,%1},[%2];" : "=l"(a0),"=l"(a1) : "r"(a_off));     \
            asm("ld.shared.v2.b64 {%0,%1},[%2];" : "=l"(a2),"=l"(a3) : "r"(a_off+16u)); \
            asm("ld.shared.v2.b64 {%0,%1},[%2];" : "=l"(a4),"=l"(a5) : "r"(a_off+32u)); \
            asm("ld.shared.v2.b64 {%0,%1},[%2];" : "=l"(a6),"=l"(a7) : "r"(a_off+48u)); \
            asm("ld.shared.v2.b64 {%0,%1},[%2];" : "=l"(a8),"=l"(a9) : "r"(a_off+64u)); \
            ffma2(acc[0], a0, QQ); ffma2(acc[1], a1, QQ);                               \
            ffma2(acc[2], a2, QQ); ffma2(acc[3], a3, QQ);                               \
            ffma2(acc[4], a4, QQ); ffma2(acc[5], a5, QQ);                               \
            ffma2(acc[6], a6, QQ); ffma2(acc[7], a7, QQ);                               \
            ffma2(acc[8], a8, QQ); ffma2(acc[9], a9, QQ);                               \
        } while (0)

        {
            const int UNR = 4;
            int k = k0;
            const int kmain = k0 + ((k1 - k0) / UNR) * UNR;
            float qv[UNR];
            if (k < kmain) {
                #pragma unroll
                for (int i = 0; i < UNR; i++) qv[i] = __ldcg(qr + (k + i) * HH + lane);
            }
            while (k < kmain) {
                const int knext = k + UNR;
                float qn[UNR];
                if (knext < kmain) {
                    #pragma unroll
                    for (int i = 0; i < UNR; i++) qn[i] = __ldcg(qr + (knext + i) * HH + lane);
                }
                #pragma unroll
                for (int i = 0; i < UNR; i++) {
                    const unsigned long long qq = pack2(qv[i], qv[i]);
                    ADJ_FMA(k + i, qq);
                }
                #pragma unroll
                for (int i = 0; i < UNR; i++) qv[i] = qn[i];
                k = knext;
            }
            for (; k < k1; ++k) {
                const float q1 = __ldcg(qr + k * HH + lane);
                const unsigned long long qq = pack2(q1, q1);
                ADJ_FMA(k, qq);
            }
        }
        #undef ADJ_FMA

        // ---- overlapped with other warps' adj: stage x_{t+1}, gates_t (activated) ----
        const float* xcur = xsbuf + (t & 1) * ROWS * DD;
        float* xnext      = xsbuf + ((t + 1) & 1) * ROWS * DD;
        if (t + 1 < TT) {
            for (int e = tid; e < ROWS * DD; e += NTHREADS)
                xnext[e] = x[(size_t)(row0 + e / DD) * (TT * DD) + (t + 1) * DD + (e & (DD - 1))];
        }
        gates_act(tid, xcur, hs, g4s, W_ih, W_hh, b);

        // ---- reduction: 4 chains, pairwise named barriers ----
        {
            const int s = wid & 3;
            if (wid >= 12) {
                float* rb = red + s * ROWS * HH;
                #pragma unroll
                for (int j = 0; j < ROWS / 2; j++) {
                    const float2 v = unpack2(acc[j]);
                    rb[(2 * j) * HH + lane]     = v.x;
                    rb[(2 * j + 1) * HH + lane] = v.y;
                }
                named_bar(1 + s);
            } else if (wid >= 8) {
                named_bar(1 + s);
                float* rb = red + s * ROWS * HH;
                #pragma unroll
                for (int j = 0; j < ROWS / 2; j++) {
                    const float2 v = unpack2(acc[j]);
                    rb[(2 * j) * HH + lane]     += v.x;
                    rb[(2 * j + 1) * HH + lane] += v.y;
                }
                named_bar(5 + s);
            } else if (wid >= 4) {
                named_bar(5 + s);
                float* rb = red + s * ROWS * HH;
                #pragma unroll
                for (int j = 0; j < ROWS / 2; j++) {
                    const float2 v = unpack2(acc[j]);
                    rb[(2 * j) * HH + lane]     += v.x;
                    rb[(2 * j + 1) * HH + lane] += v.y;
                }
                named_bar(9 + s);
            } else {
                named_bar(9 + s);
                float* rb = red + s * ROWS * HH;
                #pragma unroll
                for (int j = 0; j < ROWS / 2; j++) {
                    const float2 v = unpack2(acc[j]);
                    rb[(2 * j) * HH + lane]     += v.x;
                    rb[(2 * j + 1) * HH + lane] += v.y;
                }
            }
        }
        __syncthreads();   // red + g4s complete

        // ---- LSTM epilogue (gates pre-activated) ----
        for (int e = tid; e < ROWS * HH; e += NTHREADS) {
            const int m = e >> 5, n = e & 31;
            const float aggv = red[m * HH + n]
                             + red[1 * ROWS * HH + m * HH + n]
                             + red[2 * ROWS * HH + m * HH + n]
                             + red[3 * ROWS * HH + m * HH + n];
            const float iv = g4s[m * G4 + n];
            const float fv = g4s[m * G4 + HH + n];
            const float gv = g4s[m * G4 + 2 * HH + n];
            const float ov = g4s[m * G4 + 3 * HH + n];
            const float cv = fv * (cs[e] + aggv) + iv * gv;
            cs[e] = cv;
            hs[e] = ov * tanh_f(cv);
        }
        __syncthreads();

        // ---- dense head ----
        if (tid < ROWS) {
            float a = b_d[0];
            #pragma unroll
            for (int n = 0; n < HH; n++) a += hs[tid * HH + n] * W_d[n];
            out[(size_t)(row0 + tid) * TT + t] = a;
        }

        if (t + 1 < TT) {
            q_prep(tid, row0, hs, W_q, b_q, g_q[(t + 1) & 1]);
            grid_barrier((unsigned)(t + 2));
        }
    }
}

extern "C" void kernel_launch(void* const* d_in, const int* in_sizes, int n_in,
                              void* d_out, int out_size) {
    (void)in_sizes; (void)n_in; (void)out_size;
    const float* x    = (const float*)d_in[0];
    const float* adj  = (const float*)d_in[1];
    const float* W_ih = (const float*)d_in[2];
    const float* W_hh = (const float*)d_in[3];
    const float* b    = (const float*)d_in[4];
    const float* W_q  = (const float*)d_in[5];
    const float* b_q  = (const float*)d_in[6];
    const float* W_d  = (const float*)d_in[7];
    const float* b_d  = (const float*)d_in[8];
    float* out = (float*)d_out;

    cudaFuncSetAttribute(rgcn_kernel,
                         cudaFuncAttributeMaxDynamicSharedMemorySize, SMEM_BYTES);
    rgcn_reset<<<1, 1>>>();
    rgcn_kernel<<<NCTA, NTHREADS, SMEM_BYTES>>>(x, adj, W_ih, W_hh, b,
                                                W_q, b_q, W_d, b_d, out);
}